// round 2
// baseline (speedup 1.0000x reference)
#include <cuda_runtime.h>

#define B_TOTAL 32768
#define D   256
#define H1  512
#define H2  256
#define E   16
#define O   64
#define BT  32
#define THREADS 512
#define XPAD 36   // padded row stride (floats)

// SMEM layout (floats):
//   x_t   [D][XPAD]    : x tile transposed, x_t[d][b]
//   h1t   [H1][XPAD]   : relu(h1) transposed
//   h2t   [H2][XPAD]   : relu(h2) transposed
//   gates [BT][E]
#define SMEM_FLOATS (D*XPAD + H1*XPAD + H2*XPAD + BT*E)

typedef unsigned long long u64;

// packed f32x2 helpers (sm_103a)
__device__ __forceinline__ u64 f2_dup(float v) {
    u64 r; asm("mov.b64 %0, {%1, %1};" : "=l"(r) : "f"(v)); return r;
}
__device__ __forceinline__ void f2_fma(u64& d, u64 a, u64 b) {
    asm("fma.rn.f32x2 %0, %1, %2, %0;" : "+l"(d) : "l"(a), "l"(b));
}
__device__ __forceinline__ void f2_unpack(u64 v, float& lo, float& hi) {
    asm("mov.b64 {%0, %1}, %2;" : "=f"(lo), "=f"(hi) : "l"(v));
}

__global__ __launch_bounds__(THREADS, 1)
void moe_yts_fused_kernel(const float* __restrict__ x,
                          const float* __restrict__ gate_w,
                          const float* __restrict__ gate_b,
                          const float* __restrict__ W1,
                          const float* __restrict__ b1,
                          const float* __restrict__ W2,
                          const float* __restrict__ b2,
                          const float* __restrict__ W3,
                          const float* __restrict__ b3,
                          const float* __restrict__ head_w,
                          const float* __restrict__ head_b,
                          float* __restrict__ out)
{
    extern __shared__ float smem[];
    float* x_t     = smem;                  // [D][XPAD]
    float* h1t     = x_t + D * XPAD;        // [H1][XPAD]
    float* h2t     = h1t + H1 * XPAD;       // [H2][XPAD]
    float* gates_s = h2t + H2 * XPAD;       // [BT][E]

    const int t      = threadIdx.x;
    const int b_base = blockIdx.x * BT;

    // ---- Load x tile [BT, D] transposed into SMEM ----
    for (int idx = t; idx < BT * (D / 4); idx += THREADS) {
        int row = idx >> 6;
        int c4  = idx & 63;
        float4 v = *(const float4*)(x + (size_t)(b_base + row) * D + c4 * 4);
        x_t[(c4 * 4 + 0) * XPAD + row] = v.x;
        x_t[(c4 * 4 + 1) * XPAD + row] = v.y;
        x_t[(c4 * 4 + 2) * XPAD + row] = v.z;
        x_t[(c4 * 4 + 3) * XPAD + row] = v.w;
    }
    __syncthreads();

    // ---- Gate logits ----
    {
        int b = t >> 4;
        int e = t & 15;
        float acc = gate_b[e];
        #pragma unroll 8
        for (int d = 0; d < D; d++)
            acc = fmaf(x_t[d * XPAD + b], gate_w[d * E + e], acc);
        gates_s[b * E + e] = acc;
    }
    __syncthreads();
    if (t < BT) {
        float* row = gates_s + t * E;
        float m = row[0];
        #pragma unroll
        for (int e = 1; e < E; e++) m = fmaxf(m, row[e]);
        float s = 0.f;
        #pragma unroll
        for (int e = 0; e < E; e++) { float v = expf(row[e] - m); row[e] = v; s += v; }
        float inv = 1.0f / s;
        #pragma unroll
        for (int e = 0; e < E; e++) row[e] *= inv;
    }
    __syncthreads();

    // ---- Thread roles ----
    // GEMM1: 64 h-groups (8 h each) x 8 b-groups (4 b each)
    const int hgA = t & 63, bgA = t >> 6;
    const int hA0 = hgA * 8, bA0 = bgA * 4;
    // GEMM2: 32 k-groups (8 k each) x 16 b-groups (2 b each)
    const int kgB = t & 31, bgB = t >> 5;
    const int kB0 = kgB * 8, bB0 = bgB * 2;
    // GEMM3: 16 o-groups (4 o each) x 32 b-rows
    const int og  = t & 15,  bC  = t >> 4;
    const int o0  = og * 4;

    float fused[4] = {0.f, 0.f, 0.f, 0.f};

    for (int e = 0; e < E; e++) {
        // ============ GEMM1: h1 = relu(x @ W1[e] + b1[e]) ============
        // acc[i=4 b][j=4 pairs of h]; weights as native u64 pairs from LDG.128
        {
            u64 acc[4][4];
            #pragma unroll
            for (int i = 0; i < 4; i++)
                #pragma unroll
                for (int j = 0; j < 4; j++) acc[i][j] = 0ull;

            const u64* w1p = (const u64*)(W1 + (size_t)e * D * H1 + hA0);
            #pragma unroll 4
            for (int d = 0; d < D; d++) {
                float4 xv = *(const float4*)(x_t + d * XPAD + bA0);
                u64 xd[4] = {f2_dup(xv.x), f2_dup(xv.y), f2_dup(xv.z), f2_dup(xv.w)};
                const u64* wr = w1p + (size_t)d * (H1 / 2);
                ulonglong2 wa = *(const ulonglong2*)(wr);
                ulonglong2 wb = *(const ulonglong2*)(wr + 2);
                u64 wj[4] = {wa.x, wa.y, wb.x, wb.y};
                #pragma unroll
                for (int i = 0; i < 4; i++)
                    #pragma unroll
                    for (int j = 0; j < 4; j++)
                        f2_fma(acc[i][j], xd[i], wj[j]);
            }
            // epilogue: unpack, +bias, relu, store transposed
            const float* bb = b1 + e * H1 + hA0;
            #pragma unroll
            for (int j = 0; j < 4; j++) {
                float blo = bb[2 * j], bhi = bb[2 * j + 1];
                float* dlo = h1t + (hA0 + 2 * j)     * XPAD + bA0;
                float* dhi = h1t + (hA0 + 2 * j + 1) * XPAD + bA0;
                #pragma unroll
                for (int i = 0; i < 4; i++) {
                    float vlo, vhi;
                    f2_unpack(acc[i][j], vlo, vhi);
                    dlo[i] = fmaxf(vlo + blo, 0.f);
                    dhi[i] = fmaxf(vhi + bhi, 0.f);
                }
            }
        }
        __syncthreads();

        // ============ GEMM2: h2 = relu(h1 @ W2[e] + b2[e]) ============
        // acc[i=2 b][j=4 pairs of k]
        {
            u64 acc[2][4];
            #pragma unroll
            for (int i = 0; i < 2; i++)
                #pragma unroll
                for (int j = 0; j < 4; j++) acc[i][j] = 0ull;

            const u64* w2p = (const u64*)(W2 + (size_t)e * H1 * H2 + kB0);
            #pragma unroll 4
            for (int h = 0; h < H1; h++) {
                float2 xv = *(const float2*)(h1t + h * XPAD + bB0);
                u64 x0 = f2_dup(xv.x), x1 = f2_dup(xv.y);
                const u64* wr = w2p + (size_t)h * (H2 / 2);
                ulonglong2 wa = *(const ulonglong2*)(wr);
                ulonglong2 wb = *(const ulonglong2*)(wr + 2);
                u64 wj[4] = {wa.x, wa.y, wb.x, wb.y};
                #pragma unroll
                for (int j = 0; j < 4; j++) {
                    f2_fma(acc[0][j], x0, wj[j]);
                    f2_fma(acc[1][j], x1, wj[j]);
                }
            }
            const float* bb = b2 + e * H2 + kB0;
            #pragma unroll
            for (int j = 0; j < 4; j++) {
                float blo = bb[2 * j], bhi = bb[2 * j + 1];
                float* dlo = h2t + (kB0 + 2 * j)     * XPAD + bB0;
                float* dhi = h2t + (kB0 + 2 * j + 1) * XPAD + bB0;
                #pragma unroll
                for (int i = 0; i < 2; i++) {
                    float vlo, vhi;
                    f2_unpack(acc[i][j], vlo, vhi);
                    dlo[i] = fmaxf(vlo + blo, 0.f);
                    dhi[i] = fmaxf(vhi + bhi, 0.f);
                }
            }
        }
        __syncthreads();

        // ======= GEMM3: eo = h2 @ W3[e] + b3; fused += g * eo =======
        {
            u64 a3[2] = {0ull, 0ull};
            const u64* w3p = (const u64*)(W3 + (size_t)e * H2 * O + o0);
            #pragma unroll 4
            for (int k = 0; k < H2; k++) {
                float hv = h2t[k * XPAD + bC];
                u64 hd = f2_dup(hv);
                ulonglong2 w = *(const ulonglong2*)(w3p + (size_t)k * (O / 2));
                f2_fma(a3[0], hd, w.x);
                f2_fma(a3[1], hd, w.y);
            }
            float4 bb = *(const float4*)(b3 + e * O + o0);
            float g = gates_s[bC * E + e];
            float v0, v1, v2, v3;
            f2_unpack(a3[0], v0, v1);
            f2_unpack(a3[1], v2, v3);
            fused[0] = fmaf(g, v0 + bb.x, fused[0]);
            fused[1] = fmaf(g, v1 + bb.y, fused[1]);
            fused[2] = fmaf(g, v2 + bb.z, fused[2]);
            fused[3] = fmaf(g, v3 + bb.w, fused[3]);
        }
        __syncthreads();
    }

    // ---- Head ----
    {
        float4 hw = *(const float4*)(head_w + o0);
        float p = fused[0] * hw.x + fused[1] * hw.y + fused[2] * hw.z + fused[3] * hw.w;
        #pragma unroll
        for (int off = 8; off >= 1; off >>= 1)
            p += __shfl_xor_sync(0xffffffffu, p, off);
        if (og == 0)
            out[b_base + bC] = p + head_b[0];
    }
}

extern "C" void kernel_launch(void* const* d_in, const int* in_sizes, int n_in,
                              void* d_out, int out_size) {
    const float* x      = (const float*)d_in[0];
    const float* gate_w = (const float*)d_in[1];
    const float* gate_b = (const float*)d_in[2];
    const float* W1     = (const float*)d_in[3];
    const float* b1     = (const float*)d_in[4];
    const float* W2     = (const float*)d_in[5];
    const float* b2     = (const float*)d_in[6];
    const float* W3     = (const float*)d_in[7];
    const float* b3     = (const float*)d_in[8];
    const float* head_w = (const float*)d_in[9];
    const float* head_b = (const float*)d_in[10];
    float* out = (float*)d_out;

    const size_t smem_bytes = (size_t)SMEM_FLOATS * sizeof(float); // 149504 B
    cudaFuncSetAttribute(moe_yts_fused_kernel,
                         cudaFuncAttributeMaxDynamicSharedMemorySize,
                         (int)smem_bytes);

    moe_yts_fused_kernel<<<B_TOTAL / BT, THREADS, smem_bytes>>>(
        x, gate_w, gate_b, W1, b1, W2, b2, W3, b3, head_w, head_b, out);
}

// round 3
// speedup vs baseline: 1.6010x; 1.6010x over previous
#include <cuda_runtime.h>

#define B_TOTAL 32768
#define D   256
#define H1  512
#define H2  256
#define E   16
#define O   64
#define BT  32
#define THREADS 512
#define XPAD 36   // padded row stride (floats)

// SMEM layout (floats):
//   x_t   [D][XPAD], h1t [H1][XPAD], h2t [H2][XPAD], gates [BT][E]
#define SMEM_FLOATS (D*XPAD + H1*XPAD + H2*XPAD + BT*E)

typedef unsigned long long u64;

__device__ __forceinline__ u64 f2_dup(float v) {
    u64 r; asm("mov.b64 %0, {%1, %1};" : "=l"(r) : "f"(v)); return r;
}
__device__ __forceinline__ void f2_fma(u64& d, u64 a, u64 b) {
    asm("fma.rn.f32x2 %0, %1, %2, %0;" : "+l"(d) : "l"(a), "l"(b));
}
__device__ __forceinline__ void f2_unpack(u64 v, float& lo, float& hi) {
    asm("mov.b64 {%0, %1}, %2;" : "=f"(lo), "=f"(hi) : "l"(v));
}

__global__ __launch_bounds__(THREADS, 1)
void moe_yts_fused_kernel(const float* __restrict__ x,
                          const float* __restrict__ gate_w,
                          const float* __restrict__ gate_b,
                          const float* __restrict__ W1,
                          const float* __restrict__ b1,
                          const float* __restrict__ W2,
                          const float* __restrict__ b2,
                          const float* __restrict__ W3,
                          const float* __restrict__ b3,
                          const float* __restrict__ head_w,
                          const float* __restrict__ head_b,
                          float* __restrict__ out)
{
    extern __shared__ float smem[];
    float* x_t     = smem;                  // [D][XPAD]
    float* h1t     = x_t + D * XPAD;        // [H1][XPAD]
    float* h2t     = h1t + H1 * XPAD;       // [H2][XPAD]
    float* gates_s = h2t + H2 * XPAD;       // [BT][E]

    const int t      = threadIdx.x;
    const int b_base = blockIdx.x * BT;

    // ---- Load x tile [BT, D] transposed into SMEM ----
    for (int idx = t; idx < BT * (D / 4); idx += THREADS) {
        int row = idx >> 6;
        int c4  = idx & 63;
        float4 v = *(const float4*)(x + (size_t)(b_base + row) * D + c4 * 4);
        x_t[(c4 * 4 + 0) * XPAD + row] = v.x;
        x_t[(c4 * 4 + 1) * XPAD + row] = v.y;
        x_t[(c4 * 4 + 2) * XPAD + row] = v.z;
        x_t[(c4 * 4 + 3) * XPAD + row] = v.w;
    }
    __syncthreads();

    // ---- Gate logits ----
    {
        int b = t >> 4;
        int e = t & 15;
        float acc = gate_b[e];
        #pragma unroll 8
        for (int d = 0; d < D; d++)
            acc = fmaf(x_t[d * XPAD + b], gate_w[d * E + e], acc);
        gates_s[b * E + e] = acc;
    }
    __syncthreads();
    if (t < BT) {
        float* row = gates_s + t * E;
        float m = row[0];
        #pragma unroll
        for (int e = 1; e < E; e++) m = fmaxf(m, row[e]);
        float s = 0.f;
        #pragma unroll
        for (int e = 0; e < E; e++) { float v = expf(row[e] - m); row[e] = v; s += v; }
        float inv = 1.0f / s;
        #pragma unroll
        for (int e = 0; e < E; e++) row[e] *= inv;
    }
    __syncthreads();

    // ---- Thread roles ----
    // GEMM1: 128 h-groups (4 h) x 4 b-groups (8 b = 4 native pairs)
    const int hgA = t & 127, bgA = t >> 7;
    const int hA0 = hgA * 4, bA0 = bgA * 8;
    // GEMM2: 128 k-groups (2 k) x 4 b-groups (8 b = 4 native pairs)
    const int kgB = t & 127, bgB = t >> 7;
    const int kB0 = kgB * 2, bB0 = bgB * 8;
    // GEMM3: 16 o-groups (4 o = 2 native w-pairs) x 32 b-rows
    const int og  = t & 15,  bC  = t >> 4;
    const int o0  = og * 4;

    float fused[4] = {0.f, 0.f, 0.f, 0.f};

    for (int e = 0; e < E; e++) {
        // ===== GEMM1: h1 = relu(x @ W1[e] + b1[e]) =====
        // acc[i = 4 b-pairs][j = 4 h]; x pairs native from LDS.128; dup weights.
        {
            u64 acc[4][4];
            #pragma unroll
            for (int i = 0; i < 4; i++)
                #pragma unroll
                for (int j = 0; j < 4; j++) acc[i][j] = 0ull;

            const float* w1p = W1 + (size_t)e * D * H1 + hA0;
            #pragma unroll 4
            for (int d = 0; d < D; d++) {
                const ulonglong2* xp = (const ulonglong2*)(x_t + d * XPAD + bA0);
                ulonglong2 xa = xp[0], xb = xp[1];
                u64 xi[4] = {xa.x, xa.y, xb.x, xb.y};
                float4 w = *(const float4*)(w1p + (size_t)d * H1);
                u64 wd[4] = {f2_dup(w.x), f2_dup(w.y), f2_dup(w.z), f2_dup(w.w)};
                #pragma unroll
                for (int j = 0; j < 4; j++)
                    #pragma unroll
                    for (int i = 0; i < 4; i++)
                        f2_fma(acc[i][j], xi[i], wd[j]);
            }
            float4 bb = *(const float4*)(b1 + e * H1 + hA0);
            float bj[4] = {bb.x, bb.y, bb.z, bb.w};
            #pragma unroll
            for (int j = 0; j < 4; j++) {
                float* dst = h1t + (hA0 + j) * XPAD + bA0;
                #pragma unroll
                for (int i = 0; i < 4; i++) {
                    float vlo, vhi;
                    f2_unpack(acc[i][j], vlo, vhi);
                    float2 st = make_float2(fmaxf(vlo + bj[j], 0.f),
                                            fmaxf(vhi + bj[j], 0.f));
                    *(float2*)(dst + 2 * i) = st;
                }
            }
        }
        __syncthreads();

        // ===== GEMM2: h2 = relu(h1 @ W2[e] + b2[e]) =====
        // acc[i = 4 b-pairs][j = 2 k]; h1 pairs native; dup 2 weights (LDG.64).
        {
            u64 acc[4][2];
            #pragma unroll
            for (int i = 0; i < 4; i++) { acc[i][0] = 0ull; acc[i][1] = 0ull; }

            const float* w2p = W2 + (size_t)e * H1 * H2 + kB0;
            #pragma unroll 4
            for (int h = 0; h < H1; h++) {
                const ulonglong2* xp = (const ulonglong2*)(h1t + h * XPAD + bB0);
                ulonglong2 xa = xp[0], xb = xp[1];
                u64 xi[4] = {xa.x, xa.y, xb.x, xb.y};
                float2 w = *(const float2*)(w2p + (size_t)h * H2);
                u64 w0 = f2_dup(w.x), w1 = f2_dup(w.y);
                #pragma unroll
                for (int i = 0; i < 4; i++) {
                    f2_fma(acc[i][0], xi[i], w0);
                    f2_fma(acc[i][1], xi[i], w1);
                }
            }
            float2 bb = *(const float2*)(b2 + e * H2 + kB0);
            float bj[2] = {bb.x, bb.y};
            #pragma unroll
            for (int j = 0; j < 2; j++) {
                float* dst = h2t + (kB0 + j) * XPAD + bB0;
                #pragma unroll
                for (int i = 0; i < 4; i++) {
                    float vlo, vhi;
                    f2_unpack(acc[i][j], vlo, vhi);
                    float2 st = make_float2(fmaxf(vlo + bj[j], 0.f),
                                            fmaxf(vhi + bj[j], 0.f));
                    *(float2*)(dst + 2 * i) = st;
                }
            }
        }
        __syncthreads();

        // ===== GEMM3: eo = h2 @ W3[e] + b3; fused += g * eo =====
        // pack along o: native weight pairs from LDG.128, dup h scalar.
        {
            u64 a3[2] = {0ull, 0ull};
            const u64* w3p = (const u64*)(W3 + (size_t)e * H2 * O + o0);
            #pragma unroll 4
            for (int k = 0; k < H2; k++) {
                float hv = h2t[k * XPAD + bC];
                u64 hd = f2_dup(hv);
                ulonglong2 w = *(const ulonglong2*)(w3p + (size_t)k * (O / 2));
                f2_fma(a3[0], hd, w.x);
                f2_fma(a3[1], hd, w.y);
            }
            float4 bb = *(const float4*)(b3 + e * O + o0);
            float g = gates_s[bC * E + e];
            float v0, v1, v2, v3;
            f2_unpack(a3[0], v0, v1);
            f2_unpack(a3[1], v2, v3);
            fused[0] = fmaf(g, v0 + bb.x, fused[0]);
            fused[1] = fmaf(g, v1 + bb.y, fused[1]);
            fused[2] = fmaf(g, v2 + bb.z, fused[2]);
            fused[3] = fmaf(g, v3 + bb.w, fused[3]);
        }
        __syncthreads();
    }

    // ---- Head ----
    {
        float4 hw = *(const float4*)(head_w + o0);
        float p = fused[0] * hw.x + fused[1] * hw.y + fused[2] * hw.z + fused[3] * hw.w;
        #pragma unroll
        for (int off = 8; off >= 1; off >>= 1)
            p += __shfl_xor_sync(0xffffffffu, p, off);
        if (og == 0)
            out[b_base + bC] = p + head_b[0];
    }
}

extern "C" void kernel_launch(void* const* d_in, const int* in_sizes, int n_in,
                              void* d_out, int out_size) {
    const float* x      = (const float*)d_in[0];
    const float* gate_w = (const float*)d_in[1];
    const float* gate_b = (const float*)d_in[2];
    const float* W1     = (const float*)d_in[3];
    const float* b1     = (const float*)d_in[4];
    const float* W2     = (const float*)d_in[5];
    const float* b2     = (const float*)d_in[6];
    const float* W3     = (const float*)d_in[7];
    const float* b3     = (const float*)d_in[8];
    const float* head_w = (const float*)d_in[9];
    const float* head_b = (const float*)d_in[10];
    float* out = (float*)d_out;

    const size_t smem_bytes = (size_t)SMEM_FLOATS * sizeof(float); // 149504 B
    cudaFuncSetAttribute(moe_yts_fused_kernel,
                         cudaFuncAttributeMaxDynamicSharedMemorySize,
                         (int)smem_bytes);

    moe_yts_fused_kernel<<<B_TOTAL / BT, THREADS, smem_bytes>>>(
        x, gate_w, gate_b, W1, b1, W2, b2, W3, b3, head_w, head_b, out);
}

// round 4
// speedup vs baseline: 1.6026x; 1.0010x over previous
#include <cuda_runtime.h>

#define B_TOTAL 32768
#define D   256
#define H1  512
#define H2  256
#define E   16
#define O   64
#define BT  32
#define THREADS 512
#define XPAD 36   // padded row stride (floats)

// SMEM layout (floats):
//   x_t   [D][XPAD], h1t [H1][XPAD], h2t [H2][XPAD], gates [BT][E]
#define SMEM_FLOATS (D*XPAD + H1*XPAD + H2*XPAD + BT*E)

typedef unsigned long long u64;

__device__ __forceinline__ u64 f2_dup(float v) {
    u64 r; asm("mov.b64 %0, {%1, %1};" : "=l"(r) : "f"(v)); return r;
}
__device__ __forceinline__ void f2_fma(u64& d, u64 a, u64 b) {
    asm("fma.rn.f32x2 %0, %1, %2, %0;" : "+l"(d) : "l"(a), "l"(b));
}
__device__ __forceinline__ void f2_unpack(u64 v, float& lo, float& hi) {
    asm("mov.b64 {%0, %1}, %2;" : "=f"(lo), "=f"(hi) : "l"(v));
}

__global__ __launch_bounds__(THREADS, 1)
void moe_yts_fused_kernel(const float* __restrict__ x,
                          const float* __restrict__ gate_w,
                          const float* __restrict__ gate_b,
                          const float* __restrict__ W1,
                          const float* __restrict__ b1,
                          const float* __restrict__ W2,
                          const float* __restrict__ b2,
                          const float* __restrict__ W3,
                          const float* __restrict__ b3,
                          const float* __restrict__ head_w,
                          const float* __restrict__ head_b,
                          float* __restrict__ out)
{
    extern __shared__ float smem[];
    float* x_t     = smem;                  // [D][XPAD]
    float* h1t     = x_t + D * XPAD;        // [H1][XPAD]
    float* h2t     = h1t + H1 * XPAD;       // [H2][XPAD]
    float* gates_s = h2t + H2 * XPAD;       // [BT][E]

    const int t      = threadIdx.x;
    const int b_base = blockIdx.x * BT;

    // ---- Load x tile [BT, D] transposed into SMEM ----
    for (int idx = t; idx < BT * (D / 4); idx += THREADS) {
        int row = idx >> 6;
        int c4  = idx & 63;
        float4 v = *(const float4*)(x + (size_t)(b_base + row) * D + c4 * 4);
        x_t[(c4 * 4 + 0) * XPAD + row] = v.x;
        x_t[(c4 * 4 + 1) * XPAD + row] = v.y;
        x_t[(c4 * 4 + 2) * XPAD + row] = v.z;
        x_t[(c4 * 4 + 3) * XPAD + row] = v.w;
    }
    __syncthreads();

    // ---- Gate logits ----
    {
        int b = t >> 4;
        int e = t & 15;
        float acc = gate_b[e];
        #pragma unroll 8
        for (int d = 0; d < D; d++)
            acc = fmaf(x_t[d * XPAD + b], gate_w[d * E + e], acc);
        gates_s[b * E + e] = acc;
    }
    __syncthreads();
    if (t < BT) {
        float* row = gates_s + t * E;
        float m = row[0];
        #pragma unroll
        for (int e = 1; e < E; e++) m = fmaxf(m, row[e]);
        float s = 0.f;
        #pragma unroll
        for (int e = 0; e < E; e++) { float v = expf(row[e] - m); row[e] = v; s += v; }
        float inv = 1.0f / s;
        #pragma unroll
        for (int e = 0; e < E; e++) row[e] *= inv;
    }
    __syncthreads();

    // ---- Thread roles ----
    // GEMM1: 128 h-groups (4 h) x 4 b-groups (8 b = 4 native pairs)
    const int hgA = t & 127, bgA = t >> 7;
    const int hA0 = hgA * 4, bA0 = bgA * 8;
    // GEMM2: 128 k-groups (2 k) x 4 b-groups (8 b = 4 native pairs)
    const int kgB = t & 127, bgB = t >> 7;
    const int kB0 = kgB * 2, bB0 = bgB * 8;
    // GEMM3: 16 o-groups (4 o = 2 native w-pairs) x 32 b-rows
    const int og  = t & 15,  bC  = t >> 4;
    const int o0  = og * 4;

    float fused[4] = {0.f, 0.f, 0.f, 0.f};

    for (int e = 0; e < E; e++) {
        // ===== GEMM1: h1 = relu(x @ W1[e] + b1[e]) =====
        // acc[i = 4 b-pairs][j = 4 h]; x pairs native from LDS.128; dup weights.
        {
            u64 acc[4][4];
            #pragma unroll
            for (int i = 0; i < 4; i++)
                #pragma unroll
                for (int j = 0; j < 4; j++) acc[i][j] = 0ull;

            const float* w1p = W1 + (size_t)e * D * H1 + hA0;
            #pragma unroll 4
            for (int d = 0; d < D; d++) {
                const ulonglong2* xp = (const ulonglong2*)(x_t + d * XPAD + bA0);
                ulonglong2 xa = xp[0], xb = xp[1];
                u64 xi[4] = {xa.x, xa.y, xb.x, xb.y};
                float4 w = *(const float4*)(w1p + (size_t)d * H1);
                u64 wd[4] = {f2_dup(w.x), f2_dup(w.y), f2_dup(w.z), f2_dup(w.w)};
                #pragma unroll
                for (int j = 0; j < 4; j++)
                    #pragma unroll
                    for (int i = 0; i < 4; i++)
                        f2_fma(acc[i][j], xi[i], wd[j]);
            }
            float4 bb = *(const float4*)(b1 + e * H1 + hA0);
            float bj[4] = {bb.x, bb.y, bb.z, bb.w};
            #pragma unroll
            for (int j = 0; j < 4; j++) {
                float* dst = h1t + (hA0 + j) * XPAD + bA0;
                #pragma unroll
                for (int i = 0; i < 4; i++) {
                    float vlo, vhi;
                    f2_unpack(acc[i][j], vlo, vhi);
                    float2 st = make_float2(fmaxf(vlo + bj[j], 0.f),
                                            fmaxf(vhi + bj[j], 0.f));
                    *(float2*)(dst + 2 * i) = st;
                }
            }
        }
        __syncthreads();

        // ===== GEMM2: h2 = relu(h1 @ W2[e] + b2[e]) =====
        // acc[i = 4 b-pairs][j = 2 k]; h1 pairs native; dup 2 weights (LDG.64).
        {
            u64 acc[4][2];
            #pragma unroll
            for (int i = 0; i < 4; i++) { acc[i][0] = 0ull; acc[i][1] = 0ull; }

            const float* w2p = W2 + (size_t)e * H1 * H2 + kB0;
            #pragma unroll 4
            for (int h = 0; h < H1; h++) {
                const ulonglong2* xp = (const ulonglong2*)(h1t + h * XPAD + bB0);
                ulonglong2 xa = xp[0], xb = xp[1];
                u64 xi[4] = {xa.x, xa.y, xb.x, xb.y};
                float2 w = *(const float2*)(w2p + (size_t)h * H2);
                u64 w0 = f2_dup(w.x), w1 = f2_dup(w.y);
                #pragma unroll
                for (int i = 0; i < 4; i++) {
                    f2_fma(acc[i][0], xi[i], w0);
                    f2_fma(acc[i][1], xi[i], w1);
                }
            }
            float2 bb = *(const float2*)(b2 + e * H2 + kB0);
            float bj[2] = {bb.x, bb.y};
            #pragma unroll
            for (int j = 0; j < 2; j++) {
                float* dst = h2t + (kB0 + j) * XPAD + bB0;
                #pragma unroll
                for (int i = 0; i < 4; i++) {
                    float vlo, vhi;
                    f2_unpack(acc[i][j], vlo, vhi);
                    float2 st = make_float2(fmaxf(vlo + bj[j], 0.f),
                                            fmaxf(vhi + bj[j], 0.f));
                    *(float2*)(dst + 2 * i) = st;
                }
            }
        }
        __syncthreads();

        // ===== GEMM3: eo = h2 @ W3[e] + b3; fused += g * eo =====
        // pack along o: native weight pairs from LDG.128, dup h scalar.
        {
            u64 a3[2] = {0ull, 0ull};
            const u64* w3p = (const u64*)(W3 + (size_t)e * H2 * O + o0);
            #pragma unroll 4
            for (int k = 0; k < H2; k++) {
                float hv = h2t[k * XPAD + bC];
                u64 hd = f2_dup(hv);
                ulonglong2 w = *(const ulonglong2*)(w3p + (size_t)k * (O / 2));
                f2_fma(a3[0], hd, w.x);
                f2_fma(a3[1], hd, w.y);
            }
            float4 bb = *(const float4*)(b3 + e * O + o0);
            float g = gates_s[bC * E + e];
            float v0, v1, v2, v3;
            f2_unpack(a3[0], v0, v1);
            f2_unpack(a3[1], v2, v3);
            fused[0] = fmaf(g, v0 + bb.x, fused[0]);
            fused[1] = fmaf(g, v1 + bb.y, fused[1]);
            fused[2] = fmaf(g, v2 + bb.z, fused[2]);
            fused[3] = fmaf(g, v3 + bb.w, fused[3]);
        }
        __syncthreads();
    }

    // ---- Head ----
    {
        float4 hw = *(const float4*)(head_w + o0);
        float p = fused[0] * hw.x + fused[1] * hw.y + fused[2] * hw.z + fused[3] * hw.w;
        #pragma unroll
        for (int off = 8; off >= 1; off >>= 1)
            p += __shfl_xor_sync(0xffffffffu, p, off);
        if (og == 0)
            out[b_base + bC] = p + head_b[0];
    }
}

extern "C" void kernel_launch(void* const* d_in, const int* in_sizes, int n_in,
                              void* d_out, int out_size) {
    const float* x      = (const float*)d_in[0];
    const float* gate_w = (const float*)d_in[1];
    const float* gate_b = (const float*)d_in[2];
    const float* W1     = (const float*)d_in[3];
    const float* b1     = (const float*)d_in[4];
    const float* W2     = (const float*)d_in[5];
    const float* b2     = (const float*)d_in[6];
    const float* W3     = (const float*)d_in[7];
    const float* b3     = (const float*)d_in[8];
    const float* head_w = (const float*)d_in[9];
    const float* head_b = (const float*)d_in[10];
    float* out = (float*)d_out;

    const size_t smem_bytes = (size_t)SMEM_FLOATS * sizeof(float); // 149504 B
    cudaFuncSetAttribute(moe_yts_fused_kernel,
                         cudaFuncAttributeMaxDynamicSharedMemorySize,
                         (int)smem_bytes);

    moe_yts_fused_kernel<<<B_TOTAL / BT, THREADS, smem_bytes>>>(
        x, gate_w, gate_b, W1, b1, W2, b2, W3, b3, head_w, head_b, out);
}